// round 1
// baseline (speedup 1.0000x reference)
#include <cuda_runtime.h>

// Problem constants
#define BATCH 8
#define SEQ   4096
#define DM    64
#define DS    16
#define ROWS  (BATCH*SEQ)     // 32768 timesteps total
#define CH    64              // chunk length for parallel scan
#define NCHUNK (ROWS/CH)      // 512
#define CPB   (SEQ/CH)        // 64 chunks per batch

// ---------------------------------------------------------------------------
// Device scratch (static allocations only; no cudaMalloc allowed)
// ---------------------------------------------------------------------------
__device__ float g_A [ROWS*256];   // per-step transition matrices, 33.5 MB
__device__ float g_Bx[ROWS*DS];    // per-step bias vectors Bx_t
__device__ float g_M [NCHUNK*256]; // per-chunk cumulative transition
__device__ float g_v [NCHUNK*DS];  // per-chunk cumulative offset
__device__ float g_h0[NCHUNK*DS];  // state entering each chunk

// ---------------------------------------------------------------------------
// Shared 64x256 (K=64) fp32 GEMM micro-kernel.
// Thread layout: ty = tid/32 (8 row groups of 8), tx = tid%32 (32 col groups of 8).
// xs: [64 rows][64 k] row-major, Ws: [64 k][256 cols] row-major.
// ---------------------------------------------------------------------------
__device__ __forceinline__ void gemm_tile(const float* __restrict__ xs,
                                          const float* __restrict__ Ws,
                                          int rowb, int colb, float acc[8][8])
{
#pragma unroll 4
    for (int k = 0; k < 64; k++) {
        float a[8];
#pragma unroll
        for (int i = 0; i < 8; i++) a[i] = xs[(rowb + i) * 64 + k];
        float4 b0 = *(const float4*)&Ws[k * 256 + colb];
        float4 b1 = *(const float4*)&Ws[k * 256 + colb + 4];
        float b[8] = {b0.x, b0.y, b0.z, b0.w, b1.x, b1.y, b1.z, b1.w};
#pragma unroll
        for (int i = 0; i < 8; i++)
#pragma unroll
            for (int j = 0; j < 8; j++)
                acc[i][j] += a[i] * b[j];
    }
}

// ---------------------------------------------------------------------------
// K1: compute A = x@W_A + b_A  (store to g_A)  and
//     Bx[t,n] = sum_d (x@W_B + b_B)[t, n*64+d] * x[t,d]  (store to g_Bx)
// One block handles 64 consecutive timesteps.
// ---------------------------------------------------------------------------
extern __shared__ float smem[];

__global__ __launch_bounds__(256, 1)
void k1_proj(const float* __restrict__ x,  const float* __restrict__ WA,
             const float* __restrict__ bA, const float* __restrict__ WB,
             const float* __restrict__ bB)
{
    float* xs  = smem;           // 4096 floats: x tile [64][64]
    float* Ws  = smem + 4096;    // 16384 floats: weight tile [64][256]
    float* Bxs = smem + 20480;   // 1024 floats: Bx tile [64][16]

    const int tid  = threadIdx.x;
    const int row0 = blockIdx.x * 64;

    // load x tile (float4, coalesced)
    for (int i = tid; i < 64 * 16; i += 256) {
        int r = i >> 4, c = i & 15;
        ((float4*)xs)[r * 16 + c] = ((const float4*)(x + (size_t)(row0 + r) * DM))[c];
    }
    // load W_A [64][256]
    for (int i = tid; i < 4096; i += 256)
        ((float4*)Ws)[i] = ((const float4*)WA)[i];
    __syncthreads();

    const int ty = tid >> 5, tx = tid & 31;
    const int rowb = ty * 8, colb = tx * 8;

    // ---- A = x @ W_A + b_A ----
    {
        float acc[8][8];
#pragma unroll
        for (int i = 0; i < 8; i++)
#pragma unroll
            for (int j = 0; j < 8; j++) acc[i][j] = 0.f;
        gemm_tile(xs, Ws, rowb, colb, acc);

        float bb[8];
#pragma unroll
        for (int j = 0; j < 8; j++) bb[j] = bA[colb + j];

#pragma unroll
        for (int i = 0; i < 8; i++) {
            float4 s0 = make_float4(acc[i][0] + bb[0], acc[i][1] + bb[1],
                                    acc[i][2] + bb[2], acc[i][3] + bb[3]);
            float4 s1 = make_float4(acc[i][4] + bb[4], acc[i][5] + bb[5],
                                    acc[i][6] + bb[6], acc[i][7] + bb[7]);
            float* dst = &g_A[(size_t)(row0 + rowb + i) * 256 + colb];
            ((float4*)dst)[0] = s0;
            ((float4*)dst)[1] = s1;
        }
    }

    // ---- Bx: loop over 4 column-chunks of W_B (each 256 cols = 4 n-slices) ----
    for (int c = 0; c < 4; c++) {
        __syncthreads();  // previous Ws fully consumed
        for (int i = tid; i < 4096; i += 256) {
            int rk = i >> 6, c4 = i & 63;
            ((float4*)Ws)[rk * 64 + c4] =
                ((const float4*)(WB + (size_t)rk * 1024 + c * 256))[c4];
        }
        float bb[8];
#pragma unroll
        for (int j = 0; j < 8; j++) bb[j] = bB[c * 256 + colb + j];
        __syncthreads();

        float acc[8][8];
#pragma unroll
        for (int i = 0; i < 8; i++)
#pragma unroll
            for (int j = 0; j < 8; j++) acc[i][j] = 0.f;
        gemm_tile(xs, Ws, rowb, colb, acc);

        // contract with x over d, reduce across the 8 lanes sharing one n-slice
        const int n  = c * 4 + (tx >> 3);
        const int d0 = (tx & 7) * 8;
#pragma unroll
        for (int i = 0; i < 8; i++) {
            float p = 0.f;
#pragma unroll
            for (int j = 0; j < 8; j++)
                p += (acc[i][j] + bb[j]) * xs[(rowb + i) * 64 + d0 + j];
            p += __shfl_down_sync(0xffffffffu, p, 4, 8);
            p += __shfl_down_sync(0xffffffffu, p, 2, 8);
            p += __shfl_down_sync(0xffffffffu, p, 1, 8);
            if ((tx & 7) == 0)
                Bxs[(rowb + i) * DS + n] = p;   // unique writer per (ts, n)
        }
    }
    __syncthreads();
    for (int i = tid; i < 64 * DS; i += 256)
        g_Bx[(size_t)row0 * DS + i] = Bxs[i];
}

// ---------------------------------------------------------------------------
// K2: per-chunk cumulative transition.  M <- A_t M, v <- A_t v + b_t.
// One block per chunk of 64 steps; 256 threads, thread owns M[i][j].
// ---------------------------------------------------------------------------
__global__ __launch_bounds__(256, 1)
void k2_chunk_reduce()
{
    float* As  = smem;            // 16384 floats: whole chunk of A
    float* Bxs = smem + 16384;    // 1024 floats
    float* Msh = smem + 17408;    // 16*17 padded
    float* vsh = smem + 17680;    // 16

    const int tid   = threadIdx.x;
    const int chunk = blockIdx.x;
    const size_t base = (size_t)chunk * CH;

    for (int i = tid; i < 4096; i += 256)
        ((float4*)As)[i] = ((const float4*)(g_A + base * 256))[i];
    for (int i = tid; i < 256; i += 256)
        ((float4*)Bxs)[i] = ((const float4*)(g_Bx + base * DS))[i];
    __syncthreads();

    const int i = tid >> 4, j = tid & 15;
    Msh[i * 17 + j] = As[i * 16 + j];      // M = A_0
    if (j == 0) vsh[i] = Bxs[i];           // v = b_0
    __syncthreads();

    for (int t = 1; t < CH; t++) {
        const float* Ar = As + t * 256 + i * 16;
        float s0 = 0.f, s1 = 0.f;
#pragma unroll
        for (int k = 0; k < 16; k += 2) {
            s0 += Ar[k]     * Msh[k * 17 + j];
            s1 += Ar[k + 1] * Msh[(k + 1) * 17 + j];
        }
        float nm = s0 + s1;
        float nv = 0.f;
        if (j == 0) {
            nv = Bxs[t * DS + i];
#pragma unroll
            for (int k = 0; k < 16; k++) nv += Ar[k] * vsh[k];
        }
        __syncthreads();
        Msh[i * 17 + j] = nm;
        if (j == 0) vsh[i] = nv;
        __syncthreads();
    }

    g_M[(size_t)chunk * 256 + tid] = Msh[i * 17 + j];
    if (j == 0) g_v[(size_t)chunk * DS + i] = vsh[i];
}

// ---------------------------------------------------------------------------
// K3: sequential prefix over chunk summaries (64 per batch). One block/batch.
// Writes state entering each chunk into g_h0.
// ---------------------------------------------------------------------------
__global__ __launch_bounds__(256, 1)
void k3_chunk_scan()
{
    float* Ms = smem;            // 64*256
    float* vs = smem + 16384;    // 64*16

    const int b   = blockIdx.x;
    const int tid = threadIdx.x;
    for (int i = tid; i < 4096; i += 256)
        ((float4*)Ms)[i] = ((const float4*)(g_M + (size_t)b * CPB * 256))[i];
    for (int i = tid; i < 256; i += 256)
        ((float4*)vs)[i] = ((const float4*)(g_v + (size_t)b * CPB * DS))[i];
    __syncthreads();

    if (tid < 16) {
        const int i = tid;
        float h = 0.f;
        for (int c = 0; c < CPB; c++) {
            g_h0[((size_t)b * CPB + c) * DS + i] = h;
            float acc = vs[c * DS + i];
#pragma unroll
            for (int k = 0; k < 16; k++) {
                float hk = __shfl_sync(0x0000FFFFu, h, k, 16);
                acc += Ms[c * 256 + i * 16 + k] * hk;
            }
            h = acc;
        }
    }
}

// ---------------------------------------------------------------------------
// K4: in-chunk scan (warp 0, lane i owns h_i) + fused output GEMM:
//     out[t,d] = sum_n h[t,n] * (x@W_C + b_C)[t, n*64+d]
// ---------------------------------------------------------------------------
__global__ __launch_bounds__(256, 1)
void k4_scan_out(const float* __restrict__ x, const float* __restrict__ WC,
                 const float* __restrict__ bC, float* __restrict__ out)
{
    float* big = smem;            // 16384 floats: A chunk, then W_C chunks
    float* xs  = smem + 16384;    // 4096
    float* Bxs = smem + 20480;    // 1024
    float* hsh = smem + 21504;    // 1024: h_t for the chunk

    const int tid   = threadIdx.x;
    const int chunk = blockIdx.x;
    const size_t base = (size_t)chunk * CH;

    for (int i = tid; i < 4096; i += 256)
        ((float4*)big)[i] = ((const float4*)(g_A + base * 256))[i];
    for (int i = tid; i < 256; i += 256)
        ((float4*)Bxs)[i] = ((const float4*)(g_Bx + base * DS))[i];
    for (int i = tid; i < 1024; i += 256)
        ((float4*)xs)[i] = ((const float4*)(x + base * DM))[i];
    __syncthreads();

    // sequential scan within chunk, one warp, lanes 0..15
    if (tid < 16) {
        const int i = tid;
        float h = g_h0[(size_t)chunk * DS + i];
        for (int t = 0; t < CH; t++) {
            float acc = Bxs[t * DS + i];
#pragma unroll
            for (int k = 0; k < 16; k++) {
                float hk = __shfl_sync(0x0000FFFFu, h, k, 16);
                acc += big[t * 256 + i * 16 + k] * hk;
            }
            h = acc;
            hsh[t * DS + i] = h;
        }
    }
    __syncthreads();   // hs visible; A no longer needed -> big reusable

    const int ty = tid >> 5, tx = tid & 31;
    const int rowb = ty * 8, colb = tx * 8;
    const int d0 = (tx & 7) * 8;

    float oacc[8][8];
#pragma unroll
    for (int i = 0; i < 8; i++)
#pragma unroll
        for (int j = 0; j < 8; j++) oacc[i][j] = 0.f;

    for (int c = 0; c < 4; c++) {
        __syncthreads();  // previous big fully consumed
        for (int i = tid; i < 4096; i += 256) {
            int rk = i >> 6, c4 = i & 63;
            ((float4*)big)[rk * 64 + c4] =
                ((const float4*)(WC + (size_t)rk * 1024 + c * 256))[c4];
        }
        float bb[8];
#pragma unroll
        for (int j = 0; j < 8; j++) bb[j] = bC[c * 256 + colb + j];
        __syncthreads();

        float acc[8][8];
#pragma unroll
        for (int i = 0; i < 8; i++)
#pragma unroll
            for (int j = 0; j < 8; j++) acc[i][j] = 0.f;
        gemm_tile(xs, big, rowb, colb, acc);

        const int n = c * 4 + (tx >> 3);
#pragma unroll
        for (int i = 0; i < 8; i++) {
            float hv = hsh[(rowb + i) * DS + n];
#pragma unroll
            for (int j = 0; j < 8; j++)
                oacc[i][j] += hv * (acc[i][j] + bb[j]);
        }
    }

    // reduce over the 4 lanes (tx ^ 8, tx ^ 16) that share the same d-range
#pragma unroll
    for (int i = 0; i < 8; i++)
#pragma unroll
        for (int j = 0; j < 8; j++) {
            oacc[i][j] += __shfl_xor_sync(0xffffffffu, oacc[i][j], 8);
            oacc[i][j] += __shfl_xor_sync(0xffffffffu, oacc[i][j], 16);
        }

    if (tx < 8) {
#pragma unroll
        for (int i = 0; i < 8; i++) {
            float4 s0 = make_float4(oacc[i][0], oacc[i][1], oacc[i][2], oacc[i][3]);
            float4 s1 = make_float4(oacc[i][4], oacc[i][5], oacc[i][6], oacc[i][7]);
            float* dst = out + (size_t)(base + rowb + i) * DM + d0;
            ((float4*)dst)[0] = s0;
            ((float4*)dst)[1] = s1;
        }
    }
}

// ---------------------------------------------------------------------------
// Launch
// ---------------------------------------------------------------------------
extern "C" void kernel_launch(void* const* d_in, const int* in_sizes, int n_in,
                              void* d_out, int out_size)
{
    (void)in_sizes; (void)n_in; (void)out_size;
    const float* x  = (const float*)d_in[0];
    const float* WA = (const float*)d_in[1];
    const float* bA = (const float*)d_in[2];
    const float* WB = (const float*)d_in[3];
    const float* bB = (const float*)d_in[4];
    const float* WC = (const float*)d_in[5];
    const float* bC = (const float*)d_in[6];
    float* out = (float*)d_out;

    const int s1 = (4096 + 16384 + 1024) * 4;          // 86016
    const int s2 = (16384 + 1024 + 272 + 16) * 4;      // 70784
    const int s3 = (16384 + 1024) * 4;                 // 69632
    const int s4 = (16384 + 4096 + 1024 + 1024) * 4;   // 90112

    cudaFuncSetAttribute(k1_proj,         cudaFuncAttributeMaxDynamicSharedMemorySize, s1);
    cudaFuncSetAttribute(k2_chunk_reduce, cudaFuncAttributeMaxDynamicSharedMemorySize, s2);
    cudaFuncSetAttribute(k3_chunk_scan,   cudaFuncAttributeMaxDynamicSharedMemorySize, s3);
    cudaFuncSetAttribute(k4_scan_out,     cudaFuncAttributeMaxDynamicSharedMemorySize, s4);

    k1_proj        <<<ROWS / 64, 256, s1>>>(x, WA, bA, WB, bB);
    k2_chunk_reduce<<<NCHUNK,    256, s2>>>();
    k3_chunk_scan  <<<BATCH,     256, s3>>>();
    k4_scan_out    <<<NCHUNK,    256, s4>>>(x, WC, bC, out);
}

// round 3
// speedup vs baseline: 2.0538x; 2.0538x over previous
#include <cuda_runtime.h>
#include <cstdint>

// Problem constants
#define BATCH 8
#define SEQ   4096
#define DM    64
#define DS    16
#define ROWS  (BATCH*SEQ)     // 32768 timesteps total
#define CH    64              // chunk length for parallel scan
#define NCHUNK (ROWS/CH)      // 512
#define CPB   (SEQ/CH)        // 64 chunks per batch

#define XPAD 68               // xs row stride (floats)
#define WPAD 136              // weight tile row stride (floats)
#define HPAD 17               // hs tile row stride

// ---------------------------------------------------------------------------
// Device scratch (static allocations only; no cudaMalloc allowed)
// ---------------------------------------------------------------------------
__device__ float g_A [ROWS*256];   // per-step transition matrices, 33.5 MB
__device__ float g_Bx[ROWS*DS];    // per-step bias vectors Bx_t
__device__ float g_M [NCHUNK*256]; // per-chunk cumulative transition
__device__ float g_v [NCHUNK*DS];  // per-chunk cumulative offset
__device__ float g_h0[NCHUNK*DS];  // state entering each chunk
__device__ float g_hs[ROWS*DS];    // full hidden-state sequence, 2 MB

extern __shared__ float smem[];

// ---------------------------------------------------------------------------
// tf32 helpers
// ---------------------------------------------------------------------------
__device__ __forceinline__ float tf32r(float v) {
    uint32_t o;
    asm("cvt.rna.tf32.f32 %0, %1;" : "=r"(o) : "f"(v));
    return __uint_as_float(o);
}

__device__ __forceinline__ void mma_tf32(float c[4],
                                         float a0, float a1, float a2, float a3,
                                         float b0, float b1)
{
    asm volatile(
        "mma.sync.aligned.m16n8k8.row.col.f32.tf32.tf32.f32 "
        "{%0,%1,%2,%3}, {%4,%5,%6,%7}, {%8,%9}, {%0,%1,%2,%3};\n"
        : "+f"(c[0]), "+f"(c[1]), "+f"(c[2]), "+f"(c[3])
        : "r"(__float_as_uint(a0)), "r"(__float_as_uint(a1)),
          "r"(__float_as_uint(a2)), "r"(__float_as_uint(a3)),
          "r"(__float_as_uint(b0)), "r"(__float_as_uint(b1)));
}

// ---------------------------------------------------------------------------
// K1 (tf32 tensor-core): A = x@W_A + b_A -> g_A   and
//   Bx[t,n] = sum_d (x@W_B + b_B)[t, n*64+d] * x[t,d] -> g_Bx
// Block: 64 rows, 256 threads = 8 warps as 4(m)x2(n); warp tile 16x64.
// 10 weight chunks of 128 cols: chunks 0-1 = W_A, chunks 2-9 = W_B.
// Every output element has a unique writer (A: distinct cols; Bx: distinct n).
// ---------------------------------------------------------------------------
__global__ __launch_bounds__(256, 2)
void k1_proj(const float* __restrict__ x,  const float* __restrict__ WA,
             const float* __restrict__ bA, const float* __restrict__ WB,
             const float* __restrict__ bB)
{
    float* xs_t = smem;                       // 64*XPAD  rounded-to-tf32 x
    float* xs_f = xs_t + 64 * XPAD;           // 64*XPAD  original f32 x
    float* Wt   = xs_f + 64 * XPAD;           // 64*WPAD  weight chunk (tf32)
    float* bsh  = Wt   + 64 * WPAD;           // 1280 biases (bA then bB)
    float* Bxs  = bsh  + 1280;                // 64*16

    const int tid  = threadIdx.x;
    const int row0 = blockIdx.x * 64;

    // load x tile (float4 coalesced), keep f32 copy + tf32-rounded copy
    for (int i = tid; i < 64 * 16; i += 256) {
        int r = i >> 4, c4 = i & 15;
        float4 v = ((const float4*)(x + (size_t)(row0 + r) * DM))[c4];
        ((float4*)(xs_f + r * XPAD))[c4] = v;
        float4 w = make_float4(tf32r(v.x), tf32r(v.y), tf32r(v.z), tf32r(v.w));
        ((float4*)(xs_t + r * XPAD))[c4] = w;
    }
    for (int i = tid; i < 256;  i += 256) bsh[i]        = bA[i];
    for (int i = tid; i < 1024; i += 256) bsh[256 + i]  = bB[i];
    __syncthreads();

    const int lane = tid & 31;
    const int g    = lane >> 2;     // 0..7
    const int tg   = lane & 3;      // 0..3
    const int wid  = tid >> 5;
    const int wm   = wid >> 1;      // 0..3: rows wm*16 .. +15
    const int wn   = wid & 1;       // 0..1: cols wn*64 within a 128-chunk
    const int rA0  = wm * 16 + g;   // first A-frag row
    const int rA1  = rA0 + 8;

    // A fragments for all 8 k-steps (chunk-invariant): 32 regs
    float af[8][4];
#pragma unroll
    for (int k = 0; k < 8; k++) {
        af[k][0] = xs_t[rA0 * XPAD + k * 8 + tg];
        af[k][1] = xs_t[rA1 * XPAD + k * 8 + tg];
        af[k][2] = xs_t[rA0 * XPAD + k * 8 + tg + 4];
        af[k][3] = xs_t[rA1 * XPAD + k * 8 + tg + 4];
    }

    for (int c = 0; c < 10; c++) {
        __syncthreads();  // all warps finished reading previous Wt
        const float* Wsrc;  int ldw, colbase;
        if (c < 2) { Wsrc = WA; ldw = 256;  colbase = c * 128; }
        else       { Wsrc = WB; ldw = 1024; colbase = (c - 2) * 128; }
        for (int i = tid; i < 64 * 32; i += 256) {
            int r = i >> 5, q = i & 31;
            float4 v = *(const float4*)(Wsrc + (size_t)r * ldw + colbase + q * 4);
            float4 w = make_float4(tf32r(v.x), tf32r(v.y), tf32r(v.z), tf32r(v.w));
            ((float4*)(Wt + r * WPAD))[q] = w;
        }
        __syncthreads();

        float cfr[8][4];
#pragma unroll
        for (int nt = 0; nt < 8; nt++)
#pragma unroll
            for (int j = 0; j < 4; j++) cfr[nt][j] = 0.f;

#pragma unroll
        for (int k = 0; k < 8; k++) {
#pragma unroll
            for (int nt = 0; nt < 8; nt++) {
                float b0 = Wt[(k * 8 + tg)     * WPAD + wn * 64 + nt * 8 + g];
                float b1 = Wt[(k * 8 + tg + 4) * WPAD + wn * 64 + nt * 8 + g];
                mma_tf32(cfr[nt], af[k][0], af[k][1], af[k][2], af[k][3], b0, b1);
            }
        }

        if (c < 2) {
            // A-projection: add bias, store to g_A (unique writer per element)
#pragma unroll
            for (int nt = 0; nt < 8; nt++) {
                int gcol = c * 128 + wn * 64 + nt * 8 + 2 * tg;
                float b0v = bsh[gcol], b1v = bsh[gcol + 1];
                float2 s0 = make_float2(cfr[nt][0] + b0v, cfr[nt][1] + b1v);
                float2 s1 = make_float2(cfr[nt][2] + b0v, cfr[nt][3] + b1v);
                *(float2*)&g_A[(size_t)(row0 + rA0) * 256 + gcol] = s0;
                *(float2*)&g_A[(size_t)(row0 + rA1) * 256 + gcol] = s1;
            }
        } else {
            // B-projection: contract with f32 x over d, reduce over quad.
            // Each n-slice handled by exactly one (c, wn) pair -> no races.
            const int n = (c - 2) * 2 + wn;   // 0..15
            float pg = 0.f, pg8 = 0.f;
#pragma unroll
            for (int nt = 0; nt < 8; nt++) {
                int bcol = (c - 2) * 128 + wn * 64 + nt * 8 + 2 * tg;
                int d    = nt * 8 + 2 * tg;
                float b0v = bsh[256 + bcol], b1v = bsh[256 + bcol + 1];
                pg  += (cfr[nt][0] + b0v) * xs_f[rA0 * XPAD + d]
                     + (cfr[nt][1] + b1v) * xs_f[rA0 * XPAD + d + 1];
                pg8 += (cfr[nt][2] + b0v) * xs_f[rA1 * XPAD + d]
                     + (cfr[nt][3] + b1v) * xs_f[rA1 * XPAD + d + 1];
            }
            pg  += __shfl_xor_sync(0xffffffffu, pg,  1);
            pg  += __shfl_xor_sync(0xffffffffu, pg,  2);
            pg8 += __shfl_xor_sync(0xffffffffu, pg8, 1);
            pg8 += __shfl_xor_sync(0xffffffffu, pg8, 2);
            if (tg == 0) {
                Bxs[rA0 * 16 + n] = pg;
                Bxs[rA1 * 16 + n] = pg8;
            }
        }
    }
    __syncthreads();
    for (int i = tid; i < 64 * DS; i += 256)
        g_Bx[(size_t)row0 * DS + i] = Bxs[i];
}

// ---------------------------------------------------------------------------
// K2: per-chunk cumulative transition.  M <- A_t M, v <- A_t v + b_t.
// ---------------------------------------------------------------------------
__global__ __launch_bounds__(256, 1)
void k2_chunk_reduce()
{
    float* As  = smem;            // 16384 floats
    float* Bxs = smem + 16384;    // 1024
    float* Msh = smem + 17408;    // 16*17
    float* vsh = smem + 17680;    // 16

    const int tid   = threadIdx.x;
    const int chunk = blockIdx.x;
    const size_t base = (size_t)chunk * CH;

    for (int i = tid; i < 4096; i += 256)
        ((float4*)As)[i] = ((const float4*)(g_A + base * 256))[i];
    for (int i = tid; i < 256; i += 256)
        ((float4*)Bxs)[i] = ((const float4*)(g_Bx + base * DS))[i];
    __syncthreads();

    const int i = tid >> 4, j = tid & 15;
    Msh[i * 17 + j] = As[i * 16 + j];
    if (j == 0) vsh[i] = Bxs[i];
    __syncthreads();

    for (int t = 1; t < CH; t++) {
        const float* Ar = As + t * 256 + i * 16;
        float s0 = 0.f, s1 = 0.f;
#pragma unroll
        for (int k = 0; k < 16; k += 2) {
            s0 += Ar[k]     * Msh[k * 17 + j];
            s1 += Ar[k + 1] * Msh[(k + 1) * 17 + j];
        }
        float nm = s0 + s1;
        float nv = 0.f;
        if (j == 0) {
            nv = Bxs[t * DS + i];
#pragma unroll
            for (int k = 0; k < 16; k++) nv += Ar[k] * vsh[k];
        }
        __syncthreads();
        Msh[i * 17 + j] = nm;
        if (j == 0) vsh[i] = nv;
        __syncthreads();
    }

    g_M[(size_t)chunk * 256 + tid] = Msh[i * 17 + j];
    if (j == 0) g_v[(size_t)chunk * DS + i] = vsh[i];
}

// ---------------------------------------------------------------------------
// K3: sequential prefix over chunk summaries (64 per batch). One block/batch.
// ---------------------------------------------------------------------------
__global__ __launch_bounds__(256, 1)
void k3_chunk_scan()
{
    float* Ms = smem;
    float* vs = smem + 16384;

    const int b   = blockIdx.x;
    const int tid = threadIdx.x;
    for (int i = tid; i < 4096; i += 256)
        ((float4*)Ms)[i] = ((const float4*)(g_M + (size_t)b * CPB * 256))[i];
    for (int i = tid; i < 256; i += 256)
        ((float4*)vs)[i] = ((const float4*)(g_v + (size_t)b * CPB * DS))[i];
    __syncthreads();

    if (tid < 16) {
        const int i = tid;
        float h = 0.f;
        for (int c = 0; c < CPB; c++) {
            g_h0[((size_t)b * CPB + c) * DS + i] = h;
            float acc = vs[c * DS + i];
#pragma unroll
            for (int k = 0; k < 16; k++) {
                float hk = __shfl_sync(0x0000FFFFu, h, k, 16);
                acc += Ms[c * 256 + i * 16 + k] * hk;
            }
            h = acc;
        }
    }
}

// ---------------------------------------------------------------------------
// K3b: in-chunk scan, one warp per chunk, register double-buffered A prefetch.
// Writes the full hidden-state sequence to g_hs.
// ---------------------------------------------------------------------------
__global__ __launch_bounds__(128, 8)
void k3b_scan()
{
    const int chunk = blockIdx.x * 4 + (threadIdx.x >> 5);
    const int lane  = threadIdx.x & 31;
    const int i     = lane & 15;          // lanes 16-31 duplicate lanes 0-15
    const size_t base = (size_t)chunk * CH;

    float h = g_h0[(size_t)chunk * DS + i];

    const float* Ap = g_A + base * 256 + i * 16;
    float4 a0 = ((const float4*)Ap)[0];
    float4 a1 = ((const float4*)Ap)[1];
    float4 a2 = ((const float4*)Ap)[2];
    float4 a3 = ((const float4*)Ap)[3];
    float  bx = g_Bx[base * DS + i];

#pragma unroll 4
    for (int t = 0; t < CH; t++) {
        float4 n0 = make_float4(0.f,0.f,0.f,0.f), n1 = n0, n2 = n0, n3 = n0;
        float nbx = 0.f;
        if (t < CH - 1) {
            const float* An = g_A + (base + t + 1) * 256 + i * 16;
            n0 = ((const float4*)An)[0];
            n1 = ((const float4*)An)[1];
            n2 = ((const float4*)An)[2];
            n3 = ((const float4*)An)[3];
            nbx = g_Bx[(base + t + 1) * DS + i];
        }
        float s0 = bx, s1 = 0.f, s2 = 0.f, s3 = 0.f;
        s0 += a0.x * __shfl_sync(0xffffffffu, h, 0,  32);
        s1 += a0.y * __shfl_sync(0xffffffffu, h, 1,  32);
        s2 += a0.z * __shfl_sync(0xffffffffu, h, 2,  32);
        s3 += a0.w * __shfl_sync(0xffffffffu, h, 3,  32);
        s0 += a1.x * __shfl_sync(0xffffffffu, h, 4,  32);
        s1 += a1.y * __shfl_sync(0xffffffffu, h, 5,  32);
        s2 += a1.z * __shfl_sync(0xffffffffu, h, 6,  32);
        s3 += a1.w * __shfl_sync(0xffffffffu, h, 7,  32);
        s0 += a2.x * __shfl_sync(0xffffffffu, h, 8,  32);
        s1 += a2.y * __shfl_sync(0xffffffffu, h, 9,  32);
        s2 += a2.z * __shfl_sync(0xffffffffu, h, 10, 32);
        s3 += a2.w * __shfl_sync(0xffffffffu, h, 11, 32);
        s0 += a3.x * __shfl_sync(0xffffffffu, h, 12, 32);
        s1 += a3.y * __shfl_sync(0xffffffffu, h, 13, 32);
        s2 += a3.z * __shfl_sync(0xffffffffu, h, 14, 32);
        s3 += a3.w * __shfl_sync(0xffffffffu, h, 15, 32);
        h = (s0 + s1) + (s2 + s3);
        if (lane < 16) g_hs[(base + t) * DS + i] = h;
        a0 = n0; a1 = n1; a2 = n2; a3 = n3; bx = nbx;
    }
}

// ---------------------------------------------------------------------------
// K4 (tf32 tensor-core): CP = x@W_C + b_C, out[t,d] = sum_n h[t,n]*CP[t,n,d]
// FIXED: warps wn=0 and wn=1 cover the same rows/cols but different n-slices;
// their partial sums are now combined through shared memory (previously they
// raced on the same out elements -> rel_err ~ sqrt(1/2)).
// ---------------------------------------------------------------------------
__global__ __launch_bounds__(256, 2)
void k4_out(const float* __restrict__ x, const float* __restrict__ WC,
            const float* __restrict__ bC, float* __restrict__ out)
{
    float* xs_t = smem;                       // 64*XPAD
    float* Wt   = xs_t + 64 * XPAD;           // 64*WPAD  (also reduction buf)
    float* hsh  = Wt   + 64 * WPAD;           // 64*HPAD
    float* bsh  = hsh  + 64 * HPAD;           // 1024

    const int tid  = threadIdx.x;
    const int row0 = blockIdx.x * 64;

    for (int i = tid; i < 64 * 16; i += 256) {
        int r = i >> 4, c4 = i & 15;
        float4 v = ((const float4*)(x + (size_t)(row0 + r) * DM))[c4];
        float4 w = make_float4(tf32r(v.x), tf32r(v.y), tf32r(v.z), tf32r(v.w));
        ((float4*)(xs_t + r * XPAD))[c4] = w;
    }
    for (int i = tid; i < 1024; i += 256) {
        int r = i >> 4, nn = i & 15;
        hsh[r * HPAD + nn] = g_hs[(size_t)row0 * DS + i];
        bsh[i] = bC[i];
    }
    __syncthreads();

    const int lane = tid & 31;
    const int g    = lane >> 2;
    const int tg   = lane & 3;
    const int wid  = tid >> 5;
    const int wm   = wid >> 1;
    const int wn   = wid & 1;
    const int rA0  = wm * 16 + g;
    const int rA1  = rA0 + 8;

    float oacc[8][4];
#pragma unroll
    for (int nt = 0; nt < 8; nt++)
#pragma unroll
        for (int j = 0; j < 4; j++) oacc[nt][j] = 0.f;

    for (int c = 0; c < 8; c++) {
        __syncthreads();
        for (int i = tid; i < 64 * 32; i += 256) {
            int r = i >> 5, q = i & 31;
            float4 v = *(const float4*)(WC + (size_t)r * 1024 + c * 128 + q * 4);
            float4 w = make_float4(tf32r(v.x), tf32r(v.y), tf32r(v.z), tf32r(v.w));
            ((float4*)(Wt + r * WPAD))[q] = w;
        }
        __syncthreads();

        float cfr[8][4];
#pragma unroll
        for (int nt = 0; nt < 8; nt++)
#pragma unroll
            for (int j = 0; j < 4; j++) cfr[nt][j] = 0.f;

#pragma unroll
        for (int k = 0; k < 8; k++) {
            float a0 = xs_t[rA0 * XPAD + k * 8 + tg];
            float a1 = xs_t[rA1 * XPAD + k * 8 + tg];
            float a2 = xs_t[rA0 * XPAD + k * 8 + tg + 4];
            float a3 = xs_t[rA1 * XPAD + k * 8 + tg + 4];
#pragma unroll
            for (int nt = 0; nt < 8; nt++) {
                float b0 = Wt[(k * 8 + tg)     * WPAD + wn * 64 + nt * 8 + g];
                float b1 = Wt[(k * 8 + tg + 4) * WPAD + wn * 64 + nt * 8 + g];
                mma_tf32(cfr[nt], a0, a1, a2, a3, b0, b1);
            }
        }

        const int n  = c * 2 + wn;           // 0..15
        const float hg  = hsh[rA0 * HPAD + n];
        const float hg8 = hsh[rA1 * HPAD + n];
#pragma unroll
        for (int nt = 0; nt < 8; nt++) {
            int bcol = c * 128 + wn * 64 + nt * 8 + 2 * tg;
            float b0v = bsh[bcol], b1v = bsh[bcol + 1];
            oacc[nt][0] += hg  * (cfr[nt][0] + b0v);
            oacc[nt][1] += hg  * (cfr[nt][1] + b1v);
            oacc[nt][2] += hg8 * (cfr[nt][2] + b0v);
            oacc[nt][3] += hg8 * (cfr[nt][3] + b1v);
        }
    }

    // ---- combine the wn=0 / wn=1 partial n-sums (same rows, same cols) ----
    __syncthreads();               // everyone done reading Wt as weights
    float* red = Wt;               // reuse: 4 wm-groups x 1024 floats
    if (wn == 1) {
#pragma unroll
        for (int nt = 0; nt < 8; nt++)
            ((float4*)&red[wm * 1024 + nt * 128 + lane * 4])[0] =
                make_float4(oacc[nt][0], oacc[nt][1], oacc[nt][2], oacc[nt][3]);
    }
    __syncthreads();
    if (wn == 0) {
#pragma unroll
        for (int nt = 0; nt < 8; nt++) {
            float4 p = ((float4*)&red[wm * 1024 + nt * 128 + lane * 4])[0];
            int d = nt * 8 + 2 * tg;
            float2 s0 = make_float2(oacc[nt][0] + p.x, oacc[nt][1] + p.y);
            float2 s1 = make_float2(oacc[nt][2] + p.z, oacc[nt][3] + p.w);
            *(float2*)&out[(size_t)(row0 + rA0) * DM + d] = s0;
            *(float2*)&out[(size_t)(row0 + rA1) * DM + d] = s1;
        }
    }
}

// ---------------------------------------------------------------------------
// Launch
// ---------------------------------------------------------------------------
extern "C" void kernel_launch(void* const* d_in, const int* in_sizes, int n_in,
                              void* d_out, int out_size)
{
    (void)in_sizes; (void)n_in; (void)out_size;
    const float* x  = (const float*)d_in[0];
    const float* WA = (const float*)d_in[1];
    const float* bA = (const float*)d_in[2];
    const float* WB = (const float*)d_in[3];
    const float* bB = (const float*)d_in[4];
    const float* WC = (const float*)d_in[5];
    const float* bC = (const float*)d_in[6];
    float* out = (float*)d_out;

    const int s1 = (64*XPAD*2 + 64*WPAD + 1280 + 1024) * 4;   // 78,848 B
    const int s2 = (16384 + 1024 + 272 + 16) * 4;             // 70,784 B
    const int s3 = (16384 + 1024) * 4;                        // 69,632 B
    const int s4 = (64*XPAD + 64*WPAD + 64*HPAD + 1024) * 4;  // 60,672 B

    cudaFuncSetAttribute(k1_proj,         cudaFuncAttributeMaxDynamicSharedMemorySize, s1);
    cudaFuncSetAttribute(k2_chunk_reduce, cudaFuncAttributeMaxDynamicSharedMemorySize, s2);
    cudaFuncSetAttribute(k3_chunk_scan,   cudaFuncAttributeMaxDynamicSharedMemorySize, s3);
    cudaFuncSetAttribute(k4_out,          cudaFuncAttributeMaxDynamicSharedMemorySize, s4);

    k1_proj        <<<ROWS / 64,  256, s1>>>(x, WA, bA, WB, bB);
    k2_chunk_reduce<<<NCHUNK,     256, s2>>>();
    k3_chunk_scan  <<<BATCH,      256, s3>>>();
    k3b_scan       <<<NCHUNK / 4, 128, 0 >>>();
    k4_out         <<<ROWS / 64,  256, s4>>>(x, WC, bC, out);
}

// round 4
// speedup vs baseline: 2.2428x; 1.0920x over previous
#include <cuda_runtime.h>
#include <cstdint>

// Problem constants
#define BATCH 8
#define SEQ   4096
#define DM    64
#define DS    16
#define ROWS  (BATCH*SEQ)     // 32768 timesteps total
#define CH    64              // chunk length for parallel scan
#define NCHUNK (ROWS/CH)      // 512
#define CPB   (SEQ/CH)        // 64 chunks per batch

#define XPAD 68               // xs row stride (floats)
#define WPAD 136              // weight tile row stride (floats)
#define HPAD 17               // hs tile row stride

// ---------------------------------------------------------------------------
// Device scratch (static allocations only; no cudaMalloc allowed)
// g_A:  K1 writes per-step transition matrices A_t; K2 overwrites IN PLACE
//       with within-chunk prefix products M_t = A_t...A_0.
// g_Bx: K1 writes Bx_t; K2 overwrites IN PLACE with prefix offsets v_t.
// ---------------------------------------------------------------------------
__device__ float g_A [ROWS*256];   // 33.5 MB
__device__ float g_Bx[ROWS*DS];
__device__ float g_M [NCHUNK*256]; // per-chunk cumulative transition
__device__ float g_v [NCHUNK*DS];  // per-chunk cumulative offset
__device__ float g_h0[NCHUNK*DS];  // state entering each chunk

extern __shared__ float smem[];

// ---------------------------------------------------------------------------
// tf32 helpers
// ---------------------------------------------------------------------------
__device__ __forceinline__ float tf32r(float v) {
    uint32_t o;
    asm("cvt.rna.tf32.f32 %0, %1;" : "=r"(o) : "f"(v));
    return __uint_as_float(o);
}

__device__ __forceinline__ void mma_tf32(float c[4],
                                         float a0, float a1, float a2, float a3,
                                         float b0, float b1)
{
    asm volatile(
        "mma.sync.aligned.m16n8k8.row.col.f32.tf32.tf32.f32 "
        "{%0,%1,%2,%3}, {%4,%5,%6,%7}, {%8,%9}, {%0,%1,%2,%3};\n"
        : "+f"(c[0]), "+f"(c[1]), "+f"(c[2]), "+f"(c[3])
        : "r"(__float_as_uint(a0)), "r"(__float_as_uint(a1)),
          "r"(__float_as_uint(a2)), "r"(__float_as_uint(a3)),
          "r"(__float_as_uint(b0)), "r"(__float_as_uint(b1)));
}

// ---------------------------------------------------------------------------
// K1 (tf32 tensor-core): A = x@W_A + b_A -> g_A   and
//   Bx[t,n] = sum_d (x@W_B + b_B)[t, n*64+d] * x[t,d] -> g_Bx
// ---------------------------------------------------------------------------
__global__ __launch_bounds__(256, 2)
void k1_proj(const float* __restrict__ x,  const float* __restrict__ WA,
             const float* __restrict__ bA, const float* __restrict__ WB,
             const float* __restrict__ bB)
{
    float* xs_t = smem;                       // 64*XPAD  rounded-to-tf32 x
    float* xs_f = xs_t + 64 * XPAD;           // 64*XPAD  original f32 x
    float* Wt   = xs_f + 64 * XPAD;           // 64*WPAD  weight chunk (tf32)
    float* bsh  = Wt   + 64 * WPAD;           // 1280 biases (bA then bB)
    float* Bxs  = bsh  + 1280;                // 64*16

    const int tid  = threadIdx.x;
    const int row0 = blockIdx.x * 64;

    for (int i = tid; i < 64 * 16; i += 256) {
        int r = i >> 4, c4 = i & 15;
        float4 v = ((const float4*)(x + (size_t)(row0 + r) * DM))[c4];
        ((float4*)(xs_f + r * XPAD))[c4] = v;
        float4 w = make_float4(tf32r(v.x), tf32r(v.y), tf32r(v.z), tf32r(v.w));
        ((float4*)(xs_t + r * XPAD))[c4] = w;
    }
    for (int i = tid; i < 256;  i += 256) bsh[i]        = bA[i];
    for (int i = tid; i < 1024; i += 256) bsh[256 + i]  = bB[i];
    __syncthreads();

    const int lane = tid & 31;
    const int g    = lane >> 2;
    const int tg   = lane & 3;
    const int wid  = tid >> 5;
    const int wm   = wid >> 1;
    const int wn   = wid & 1;
    const int rA0  = wm * 16 + g;
    const int rA1  = rA0 + 8;

    float af[8][4];
#pragma unroll
    for (int k = 0; k < 8; k++) {
        af[k][0] = xs_t[rA0 * XPAD + k * 8 + tg];
        af[k][1] = xs_t[rA1 * XPAD + k * 8 + tg];
        af[k][2] = xs_t[rA0 * XPAD + k * 8 + tg + 4];
        af[k][3] = xs_t[rA1 * XPAD + k * 8 + tg + 4];
    }

    for (int c = 0; c < 10; c++) {
        __syncthreads();
        const float* Wsrc;  int ldw, colbase;
        if (c < 2) { Wsrc = WA; ldw = 256;  colbase = c * 128; }
        else       { Wsrc = WB; ldw = 1024; colbase = (c - 2) * 128; }
        for (int i = tid; i < 64 * 32; i += 256) {
            int r = i >> 5, q = i & 31;
            float4 v = *(const float4*)(Wsrc + (size_t)r * ldw + colbase + q * 4);
            float4 w = make_float4(tf32r(v.x), tf32r(v.y), tf32r(v.z), tf32r(v.w));
            ((float4*)(Wt + r * WPAD))[q] = w;
        }
        __syncthreads();

        float cfr[8][4];
#pragma unroll
        for (int nt = 0; nt < 8; nt++)
#pragma unroll
            for (int j = 0; j < 4; j++) cfr[nt][j] = 0.f;

#pragma unroll
        for (int k = 0; k < 8; k++) {
#pragma unroll
            for (int nt = 0; nt < 8; nt++) {
                float b0 = Wt[(k * 8 + tg)     * WPAD + wn * 64 + nt * 8 + g];
                float b1 = Wt[(k * 8 + tg + 4) * WPAD + wn * 64 + nt * 8 + g];
                mma_tf32(cfr[nt], af[k][0], af[k][1], af[k][2], af[k][3], b0, b1);
            }
        }

        if (c < 2) {
#pragma unroll
            for (int nt = 0; nt < 8; nt++) {
                int gcol = c * 128 + wn * 64 + nt * 8 + 2 * tg;
                float b0v = bsh[gcol], b1v = bsh[gcol + 1];
                float2 s0 = make_float2(cfr[nt][0] + b0v, cfr[nt][1] + b1v);
                float2 s1 = make_float2(cfr[nt][2] + b0v, cfr[nt][3] + b1v);
                *(float2*)&g_A[(size_t)(row0 + rA0) * 256 + gcol] = s0;
                *(float2*)&g_A[(size_t)(row0 + rA1) * 256 + gcol] = s1;
            }
        } else {
            const int n = (c - 2) * 2 + wn;
            float pg = 0.f, pg8 = 0.f;
#pragma unroll
            for (int nt = 0; nt < 8; nt++) {
                int bcol = (c - 2) * 128 + wn * 64 + nt * 8 + 2 * tg;
                int d    = nt * 8 + 2 * tg;
                float b0v = bsh[256 + bcol], b1v = bsh[256 + bcol + 1];
                pg  += (cfr[nt][0] + b0v) * xs_f[rA0 * XPAD + d]
                     + (cfr[nt][1] + b1v) * xs_f[rA0 * XPAD + d + 1];
                pg8 += (cfr[nt][2] + b0v) * xs_f[rA1 * XPAD + d]
                     + (cfr[nt][3] + b1v) * xs_f[rA1 * XPAD + d + 1];
            }
            pg  += __shfl_xor_sync(0xffffffffu, pg,  1);
            pg  += __shfl_xor_sync(0xffffffffu, pg,  2);
            pg8 += __shfl_xor_sync(0xffffffffu, pg8, 1);
            pg8 += __shfl_xor_sync(0xffffffffu, pg8, 2);
            if (tg == 0) {
                Bxs[rA0 * 16 + n] = pg;
                Bxs[rA1 * 16 + n] = pg8;
            }
        }
    }
    __syncthreads();
    for (int i = tid; i < 64 * DS; i += 256)
        g_Bx[(size_t)row0 * DS + i] = Bxs[i];
}

// ---------------------------------------------------------------------------
// K2: per-chunk prefix scan of transitions.
//   M_t = A_t * M_{t-1}, v_t = A_t * v_{t-1} + Bx_t   (M_0 = A_0, v_0 = Bx_0)
// Writes every prefix BACK IN PLACE over g_A / g_Bx (t=0 already correct),
// and the chunk summary (t=CH-1) to g_M / g_v.
// Single barrier per step via double-buffered Msh/vsh.
// ---------------------------------------------------------------------------
__global__ __launch_bounds__(256, 1)
void k2_chunk_prefix()
{
    float* As  = smem;            // 16384 floats
    float* Bxs = smem + 16384;    // 1024
    float* Msh = smem + 17408;    // 2 x 272 (16x17 padded)
    float* vsh = smem + 17952;    // 2 x 16

    const int tid   = threadIdx.x;
    const int chunk = blockIdx.x;
    const size_t base = (size_t)chunk * CH;

    for (int i = tid; i < 4096; i += 256)
        ((float4*)As)[i] = ((const float4*)(g_A + base * 256))[i];
    for (int i = tid; i < 256; i += 256)
        ((float4*)Bxs)[i] = ((const float4*)(g_Bx + base * DS))[i];
    __syncthreads();

    const int i = tid >> 4, j = tid & 15;
    Msh[i * 17 + j] = As[i * 16 + j];     // buffer 0 = M_0 = A_0
    if (j == 0) vsh[i] = Bxs[i];
    __syncthreads();

    for (int t = 1; t < CH; t++) {
        const int cur = t & 1, prev = cur ^ 1;
        const float* Ar = As + t * 256 + i * 16;
        const float* Mp = Msh + prev * 272;
        float s0 = 0.f, s1 = 0.f;
#pragma unroll
        for (int k = 0; k < 16; k += 2) {
            s0 += Ar[k]     * Mp[k * 17 + j];
            s1 += Ar[k + 1] * Mp[(k + 1) * 17 + j];
        }
        float nm = s0 + s1;
        Msh[cur * 272 + i * 17 + j] = nm;
        g_A[(base + t) * 256 + tid] = nm;         // prefix, coalesced
        if (j == 0) {
            const float* vp = vsh + prev * 16;
            float nv = Bxs[t * DS + i];
#pragma unroll
            for (int k = 0; k < 16; k++) nv += Ar[k] * vp[k];
            vsh[cur * 16 + i] = nv;
            g_Bx[(base + t) * DS + i] = nv;
        }
        __syncthreads();
    }

    const int f = (CH - 1) & 1;
    g_M[(size_t)chunk * 256 + tid] = Msh[f * 272 + i * 17 + j];
    if (j == 0) g_v[(size_t)chunk * DS + i] = vsh[f * 16 + i];
}

// ---------------------------------------------------------------------------
// K3: sequential prefix over chunk summaries (64 per batch). One block/batch.
// ---------------------------------------------------------------------------
__global__ __launch_bounds__(256, 1)
void k3_chunk_scan()
{
    float* Ms = smem;
    float* vs = smem + 16384;

    const int b   = blockIdx.x;
    const int tid = threadIdx.x;
    for (int i = tid; i < 4096; i += 256)
        ((float4*)Ms)[i] = ((const float4*)(g_M + (size_t)b * CPB * 256))[i];
    for (int i = tid; i < 256; i += 256)
        ((float4*)vs)[i] = ((const float4*)(g_v + (size_t)b * CPB * DS))[i];
    __syncthreads();

    if (tid < 16) {
        const int i = tid;
        float h = 0.f;
        for (int c = 0; c < CPB; c++) {
            g_h0[((size_t)b * CPB + c) * DS + i] = h;
            float acc = vs[c * DS + i];
#pragma unroll
            for (int k = 0; k < 16; k++) {
                float hk = __shfl_sync(0x0000FFFFu, h, k, 16);
                acc += Ms[c * 256 + i * 16 + k] * hk;
            }
            h = acc;
        }
    }
}

// ---------------------------------------------------------------------------
// K4 (tf32 tensor-core): reconstruct hs in parallel from chunk prefixes
//   h[t][i] = sum_k P[t][i][k] * h0[k] + v[t][i]
// then CP = x@W_C + b_C, out[t,d] = sum_n h[t,n]*CP[t,n,d].
// Block = 64 rows = exactly one chunk.
// ---------------------------------------------------------------------------
__global__ __launch_bounds__(256, 2)
void k4_out(const float* __restrict__ x, const float* __restrict__ WC,
            const float* __restrict__ bC, float* __restrict__ out)
{
    float* xs_t = smem;                       // 64*XPAD
    float* Wt   = xs_t + 64 * XPAD;           // 64*WPAD  (also reduction buf)
    float* hsh  = Wt   + 64 * WPAD;           // 64*HPAD
    float* bsh  = hsh  + 64 * HPAD;           // 1024
    float* h0sh = bsh  + 1024;                // 16

    const int tid  = threadIdx.x;
    const int row0 = blockIdx.x * 64;         // == chunk * CH

    for (int i = tid; i < 64 * 16; i += 256) {
        int r = i >> 4, c4 = i & 15;
        float4 v = ((const float4*)(x + (size_t)(row0 + r) * DM))[c4];
        float4 w = make_float4(tf32r(v.x), tf32r(v.y), tf32r(v.z), tf32r(v.w));
        ((float4*)(xs_t + r * XPAD))[c4] = w;
    }
    for (int i = tid; i < 1024; i += 256) bsh[i] = bC[i];
    if (tid < 16) h0sh[tid] = g_h0[(size_t)blockIdx.x * DS + tid];
    __syncthreads();

    // ---- parallel hs reconstruction from in-place prefixes ----
#pragma unroll
    for (int q = 0; q < 4; q++) {
        int idx = tid + q * 256;              // 0..1023
        int t = idx >> 4, i = idx & 15;
        const float4* P = (const float4*)&g_A[(size_t)(row0 + t) * 256 + i * 16];
        float4 p0 = P[0], p1 = P[1], p2 = P[2], p3 = P[3];
        float acc = g_Bx[(size_t)(row0 + t) * DS + i];
        acc += p0.x * h0sh[0]  + p0.y * h0sh[1]  + p0.z * h0sh[2]  + p0.w * h0sh[3];
        acc += p1.x * h0sh[4]  + p1.y * h0sh[5]  + p1.z * h0sh[6]  + p1.w * h0sh[7];
        acc += p2.x * h0sh[8]  + p2.y * h0sh[9]  + p2.z * h0sh[10] + p2.w * h0sh[11];
        acc += p3.x * h0sh[12] + p3.y * h0sh[13] + p3.z * h0sh[14] + p3.w * h0sh[15];
        hsh[t * HPAD + i] = acc;
    }
    // visibility of hsh is guaranteed by the __syncthreads at loop top below

    const int lane = tid & 31;
    const int g    = lane >> 2;
    const int tg   = lane & 3;
    const int wid  = tid >> 5;
    const int wm   = wid >> 1;
    const int wn   = wid & 1;
    const int rA0  = wm * 16 + g;
    const int rA1  = rA0 + 8;

    float oacc[8][4];
#pragma unroll
    for (int nt = 0; nt < 8; nt++)
#pragma unroll
        for (int j = 0; j < 4; j++) oacc[nt][j] = 0.f;

    for (int c = 0; c < 8; c++) {
        __syncthreads();
        for (int i = tid; i < 64 * 32; i += 256) {
            int r = i >> 5, q = i & 31;
            float4 v = *(const float4*)(WC + (size_t)r * 1024 + c * 128 + q * 4);
            float4 w = make_float4(tf32r(v.x), tf32r(v.y), tf32r(v.z), tf32r(v.w));
            ((float4*)(Wt + r * WPAD))[q] = w;
        }
        __syncthreads();

        float cfr[8][4];
#pragma unroll
        for (int nt = 0; nt < 8; nt++)
#pragma unroll
            for (int j = 0; j < 4; j++) cfr[nt][j] = 0.f;

#pragma unroll
        for (int k = 0; k < 8; k++) {
            float a0 = xs_t[rA0 * XPAD + k * 8 + tg];
            float a1 = xs_t[rA1 * XPAD + k * 8 + tg];
            float a2 = xs_t[rA0 * XPAD + k * 8 + tg + 4];
            float a3 = xs_t[rA1 * XPAD + k * 8 + tg + 4];
#pragma unroll
            for (int nt = 0; nt < 8; nt++) {
                float b0 = Wt[(k * 8 + tg)     * WPAD + wn * 64 + nt * 8 + g];
                float b1 = Wt[(k * 8 + tg + 4) * WPAD + wn * 64 + nt * 8 + g];
                mma_tf32(cfr[nt], a0, a1, a2, a3, b0, b1);
            }
        }

        const int n  = c * 2 + wn;
        const float hg  = hsh[rA0 * HPAD + n];
        const float hg8 = hsh[rA1 * HPAD + n];
#pragma unroll
        for (int nt = 0; nt < 8; nt++) {
            int bcol = c * 128 + wn * 64 + nt * 8 + 2 * tg;
            float b0v = bsh[bcol], b1v = bsh[bcol + 1];
            oacc[nt][0] += hg  * (cfr[nt][0] + b0v);
            oacc[nt][1] += hg  * (cfr[nt][1] + b1v);
            oacc[nt][2] += hg8 * (cfr[nt][2] + b0v);
            oacc[nt][3] += hg8 * (cfr[nt][3] + b1v);
        }
    }

    // combine the wn=0 / wn=1 partial n-sums (same rows, same cols)
    __syncthreads();
    float* red = Wt;
    if (wn == 1) {
#pragma unroll
        for (int nt = 0; nt < 8; nt++)
            ((float4*)&red[wm * 1024 + nt * 128 + lane * 4])[0] =
                make_float4(oacc[nt][0], oacc[nt][1], oacc[nt][2], oacc[nt][3]);
    }
    __syncthreads();
    if (wn == 0) {
#pragma unroll
        for (int nt = 0; nt < 8; nt++) {
            float4 p = ((float4*)&red[wm * 1024 + nt * 128 + lane * 4])[0];
            int d = nt * 8 + 2 * tg;
            float2 s0 = make_float2(oacc[nt][0] + p.x, oacc[nt][1] + p.y);
            float2 s1 = make_float2(oacc[nt][2] + p.z, oacc[nt][3] + p.w);
            *(float2*)&out[(size_t)(row0 + rA0) * DM + d] = s0;
            *(float2*)&out[(size_t)(row0 + rA1) * DM + d] = s1;
        }
    }
}

// ---------------------------------------------------------------------------
// Launch
// ---------------------------------------------------------------------------
extern "C" void kernel_launch(void* const* d_in, const int* in_sizes, int n_in,
                              void* d_out, int out_size)
{
    (void)in_sizes; (void)n_in; (void)out_size;
    const float* x  = (const float*)d_in[0];
    const float* WA = (const float*)d_in[1];
    const float* bA = (const float*)d_in[2];
    const float* WB = (const float*)d_in[3];
    const float* bB = (const float*)d_in[4];
    const float* WC = (const float*)d_in[5];
    const float* bC = (const float*)d_in[6];
    float* out = (float*)d_out;

    const int s1 = (64*XPAD*2 + 64*WPAD + 1280 + 1024) * 4;        // 78,848 B
    const int s2 = (16384 + 1024 + 2*272 + 2*16) * 4;              // 71,936 B
    const int s3 = (16384 + 1024) * 4;                             // 69,632 B
    const int s4 = (64*XPAD + 64*WPAD + 64*HPAD + 1024 + 16) * 4;  // 60,736 B

    cudaFuncSetAttribute(k1_proj,         cudaFuncAttributeMaxDynamicSharedMemorySize, s1);
    cudaFuncSetAttribute(k2_chunk_prefix, cudaFuncAttributeMaxDynamicSharedMemorySize, s2);
    cudaFuncSetAttribute(k3_chunk_scan,   cudaFuncAttributeMaxDynamicSharedMemorySize, s3);
    cudaFuncSetAttribute(k4_out,          cudaFuncAttributeMaxDynamicSharedMemorySize, s4);

    k1_proj        <<<ROWS / 64, 256, s1>>>(x, WA, bA, WB, bB);
    k2_chunk_prefix<<<NCHUNK,    256, s2>>>();
    k3_chunk_scan  <<<BATCH,     256, s3>>>();
    k4_out         <<<ROWS / 64, 256, s4>>>(x, WC, bC, out);
}